// round 1
// baseline (speedup 1.0000x reference)
#include <cuda_runtime.h>
#include <math.h>
#include <stdint.h>

#define T_STEPS 1024
#define BATCH   64
#define INDIM   512
#define HID     1024
#define G4      4096   // 4*HID

#define NBLK 128       // persistent blocks for recurrence
#define NH   8         // h-columns per block (1024/128)
#define KT   32        // K tile for recurrent GEMM

// -------- device scratch (static: no runtime allocation) --------
__device__ float    g_xproj[(size_t)T_STEPS * BATCH * G4];  // [T][B][4H]  (1 GiB)
__device__ float    g_h[2][BATCH * HID];                    // double-buffered h state
__device__ unsigned g_gen   = 0;
__device__ unsigned g_count = 0;

// ================= x_proj GEMM =================
// C[m][n] = sum_k X[m][k] * W[n][k] + bih[n] + bhh[n]
// M = T*B = 65536, N = 4096, K = 512. 128x128 tile, BK=8, 256 thr, 8x8 micro.
__global__ __launch_bounds__(256) void xproj_kernel(
    const float* __restrict__ X,
    const float* __restrict__ W,
    const float* __restrict__ bih,
    const float* __restrict__ bhh)
{
    __shared__ float xs[8][132];
    __shared__ float wsm[8][132];

    const int tid = threadIdx.x;
    const int tx  = tid & 15;        // col group
    const int ty  = tid >> 4;        // row group
    const size_t mb = (size_t)blockIdx.y * 128;
    const int    nb = blockIdx.x * 128;

    const int lm = tid >> 1;         // 0..127
    const int lk = (tid & 1) * 4;    // 0 or 4

    float acc[8][8];
#pragma unroll
    for (int i = 0; i < 8; i++)
#pragma unroll
        for (int jn = 0; jn < 8; jn++) acc[i][jn] = 0.f;

    for (int k0 = 0; k0 < INDIM; k0 += 8) {
        float4 xv = *(const float4*)&X[(mb + lm) * INDIM + k0 + lk];
        float4 wv = *(const float4*)&W[(size_t)(nb + lm) * INDIM + k0 + lk];
        xs[lk+0][lm] = xv.x; xs[lk+1][lm] = xv.y; xs[lk+2][lm] = xv.z; xs[lk+3][lm] = xv.w;
        wsm[lk+0][lm] = wv.x; wsm[lk+1][lm] = wv.y; wsm[lk+2][lm] = wv.z; wsm[lk+3][lm] = wv.w;
        __syncthreads();
#pragma unroll
        for (int k = 0; k < 8; k++) {
            float a[8], bb[8];
            *(float4*)&a[0]  = *(const float4*)&xs[k][ty * 4];
            *(float4*)&a[4]  = *(const float4*)&xs[k][64 + ty * 4];
            *(float4*)&bb[0] = *(const float4*)&wsm[k][tx * 4];
            *(float4*)&bb[4] = *(const float4*)&wsm[k][64 + tx * 4];
#pragma unroll
            for (int i = 0; i < 8; i++)
#pragma unroll
                for (int jn = 0; jn < 8; jn++)
                    acc[i][jn] += a[i] * bb[jn];
        }
        __syncthreads();
    }

    // bias per output column
    float bias[8];
#pragma unroll
    for (int jn = 0; jn < 8; jn++) {
        int col = (jn < 4) ? (tx * 4 + jn) : (64 + tx * 4 + (jn - 4));
        bias[jn] = bih[nb + col] + bhh[nb + col];
    }

#pragma unroll
    for (int i = 0; i < 8; i++) {
        int m_local = (i < 4) ? (ty * 4 + i) : (64 + ty * 4 + (i - 4));
        size_t row = (mb + m_local) * (size_t)G4 + nb;
        float4 v0, v1;
        v0.x = acc[i][0] + bias[0]; v0.y = acc[i][1] + bias[1];
        v0.z = acc[i][2] + bias[2]; v0.w = acc[i][3] + bias[3];
        v1.x = acc[i][4] + bias[4]; v1.y = acc[i][5] + bias[5];
        v1.z = acc[i][6] + bias[6]; v1.w = acc[i][7] + bias[7];
        *(float4*)&g_xproj[row + tx * 4]      = v0;
        *(float4*)&g_xproj[row + 64 + tx * 4] = v1;
    }
}

// ================= persistent recurrent kernel =================

__device__ __forceinline__ void grid_barrier() {
    __syncthreads();
    if (threadIdx.x == 0) {
        unsigned my = *(volatile unsigned*)&g_gen;
        __threadfence();
        unsigned arrived = atomicAdd(&g_count, 1u);
        if (arrived == NBLK - 1) {
            g_count = 0;
            __threadfence();
            atomicAdd(&g_gen, 1u);
        } else {
            while (*(volatile unsigned*)&g_gen == my) { __nanosleep(64); }
        }
        __threadfence();
    }
    __syncthreads();
}

__device__ __forceinline__ float sigmoidf_(float x) {
    return 1.0f / (1.0f + expf(-x));
}

// Block blk owns h-columns [blk*NH, blk*NH+8). Thread (j = tid&7, ty = tid>>3):
// h-index hb+j, batch rows 2*ty and 2*ty+1, all four gates. c lives in registers.
__global__ __launch_bounds__(256) void lstm_recurrent(
    const float* __restrict__ h0in,
    const float* __restrict__ c0in,
    const float* __restrict__ whh,   // [4096][1024]
    float* __restrict__ out,
    int out_size)
{
    __shared__ float hs[KT][66];     // hs[k][b]
    __shared__ float ws[KT][36];     // ws[k][j*4+g]

    const int tid = threadIdx.x;
    const int blk = blockIdx.x;
    const int hb  = blk * NH;
    const int j   = tid & 7;
    const int ty  = tid >> 3;        // 0..31
    const int b0  = 2 * ty;
    const int b1  = 2 * ty + 1;

    // weight-load assignment: cidx = j*4+g column in smem
    const int cidx = tid >> 3;             // 0..31
    const int jj   = cidx >> 2;
    const int gg   = cidx & 3;
    const int kqw  = (tid & 7) * 4;        // k offset in tile
    const size_t wbase = (size_t)(gg * HID + hb + jj) * HID + kqw;

    float creg0 = c0in[b0 * HID + hb + j];
    float creg1 = c0in[b1 * HID + hb + j];

    for (int t = 0; t < T_STEPS; t++) {
        const float* __restrict__ hread = (t == 0) ? h0in : g_h[t & 1];
        const float* xp = &g_xproj[(size_t)t * BATCH * G4];

        // init accumulators from x projection (issues LDGs early)
        float acc0[4], acc1[4];
#pragma unroll
        for (int g = 0; g < 4; g++) {
            acc0[g] = xp[(size_t)b0 * G4 + g * HID + hb + j];
            acc1[g] = xp[(size_t)b1 * G4 + g * HID + hb + j];
        }

        for (int k0 = 0; k0 < HID; k0 += KT) {
            // load h tile: 64 rows x 32 k  (2048 floats, 2 float4 per thread)
#pragma unroll
            for (int q = 0; q < 2; q++) {
                int s  = tid * 2 + q;
                int b  = s >> 3;
                int kq = (s & 7) * 4;
                float4 v = *(const float4*)&hread[b * HID + k0 + kq];
                hs[kq+0][b] = v.x; hs[kq+1][b] = v.y;
                hs[kq+2][b] = v.z; hs[kq+3][b] = v.w;
            }
            // load w tile: 32 cols x 32 k (1 float4 per thread)
            {
                float4 wv = *(const float4*)&whh[wbase + k0];
                ws[kqw+0][cidx] = wv.x; ws[kqw+1][cidx] = wv.y;
                ws[kqw+2][cidx] = wv.z; ws[kqw+3][cidx] = wv.w;
            }
            __syncthreads();
#pragma unroll
            for (int k = 0; k < KT; k++) {
                float2 hv = *(const float2*)&hs[k][2 * ty];
                float4 wv = *(const float4*)&ws[k][4 * j];
                acc0[0] += hv.x * wv.x; acc0[1] += hv.x * wv.y;
                acc0[2] += hv.x * wv.z; acc0[3] += hv.x * wv.w;
                acc1[0] += hv.y * wv.x; acc1[1] += hv.y * wv.y;
                acc1[2] += hv.y * wv.z; acc1[3] += hv.y * wv.w;
            }
            __syncthreads();
        }

        // elementwise LSTM cell (gate order: i, f, g, o)
        float i0 = sigmoidf_(acc0[0]);
        float f0 = sigmoidf_(acc0[1]);
        float g0 = tanhf(acc0[2]);
        float o0 = sigmoidf_(acc0[3]);
        creg0 = f0 * creg0 + i0 * g0;
        float hv0 = o0 * tanhf(creg0);

        float i1 = sigmoidf_(acc1[0]);
        float f1 = sigmoidf_(acc1[1]);
        float g1 = tanhf(acc1[2]);
        float o1 = sigmoidf_(acc1[3]);
        creg1 = f1 * creg1 + i1 * g1;
        float hv1 = o1 * tanhf(creg1);

        float* hw = g_h[(t + 1) & 1];
        hw[b0 * HID + hb + j] = hv0;
        hw[b1 * HID + hb + j] = hv1;

        out[((size_t)t * BATCH + b0) * HID + hb + j] = hv0;
        out[((size_t)t * BATCH + b1) * HID + hb + j] = hv1;

        if (t == T_STEPS - 1) {
            const long long need = (long long)T_STEPS * BATCH * HID + 2LL * BATCH * HID;
            if ((long long)out_size >= need) {
                size_t base = (size_t)T_STEPS * BATCH * HID;
                out[base + b0 * HID + hb + j] = hv0;
                out[base + b1 * HID + hb + j] = hv1;
                out[base + (size_t)BATCH * HID + b0 * HID + hb + j] = creg0;
                out[base + (size_t)BATCH * HID + b1 * HID + hb + j] = creg1;
            }
        } else {
            grid_barrier();
        }
    }
}

// ================= launch =================
extern "C" void kernel_launch(void* const* d_in, const int* in_sizes, int n_in,
                              void* d_out, int out_size) {
    const float* x    = (const float*)d_in[0];  // [T,B,I]
    const float* h0   = (const float*)d_in[1];  // [B,H]
    const float* c0   = (const float*)d_in[2];  // [B,H]
    const float* w_ih = (const float*)d_in[3];  // [4H,I]
    const float* w_hh = (const float*)d_in[4];  // [4H,H]
    const float* b_ih = (const float*)d_in[5];  // [4H]
    const float* b_hh = (const float*)d_in[6];  // [4H]
    float* out = (float*)d_out;

    dim3 g1(G4 / 128, (T_STEPS * BATCH) / 128);   // 32 x 512
    xproj_kernel<<<g1, 256>>>(x, w_ih, b_ih, b_hh);
    lstm_recurrent<<<NBLK, 256>>>(h0, c0, w_hh, out, out_size);
}

// round 2
// speedup vs baseline: 1.0014x; 1.0014x over previous
#include <cuda_runtime.h>
#include <math.h>
#include <stdint.h>

#define T_STEPS 1024
#define BATCH   64
#define INDIM   512
#define HID     1024
#define G4      4096   // 4*HID

#define NBLK 128       // persistent blocks for recurrence
#define NH   8         // h-columns per block (1024/128)
#define KT   32        // K tile for recurrent GEMM

// -------- device scratch (static: no runtime allocation) --------
__device__ float    g_xproj[(size_t)T_STEPS * BATCH * G4];  // [T][B][4H]  (1 GiB)
__device__ float    g_h[2][BATCH * HID];                    // double-buffered h state
__device__ unsigned g_gen   = 0;
__device__ unsigned g_count = 0;

// ================= x_proj GEMM =================
// C[m][n] = sum_k X[m][k] * W[n][k] + bih[n] + bhh[n]
// M = T*B = 65536, N = 4096, K = 512. 128x128 tile, BK=8, 256 thr, 8x8 micro.
__global__ __launch_bounds__(256) void xproj_kernel(
    const float* __restrict__ X,
    const float* __restrict__ W,
    const float* __restrict__ bih,
    const float* __restrict__ bhh)
{
    __shared__ float xs[8][132];
    __shared__ float wsm[8][132];

    const int tid = threadIdx.x;
    const int tx  = tid & 15;        // col group
    const int ty  = tid >> 4;        // row group
    const size_t mb = (size_t)blockIdx.y * 128;
    const int    nb = blockIdx.x * 128;

    const int lm = tid >> 1;         // 0..127
    const int lk = (tid & 1) * 4;    // 0 or 4

    float acc[8][8];
#pragma unroll
    for (int i = 0; i < 8; i++)
#pragma unroll
        for (int jn = 0; jn < 8; jn++) acc[i][jn] = 0.f;

    for (int k0 = 0; k0 < INDIM; k0 += 8) {
        float4 xv = *(const float4*)&X[(mb + lm) * INDIM + k0 + lk];
        float4 wv = *(const float4*)&W[(size_t)(nb + lm) * INDIM + k0 + lk];
        xs[lk+0][lm] = xv.x; xs[lk+1][lm] = xv.y; xs[lk+2][lm] = xv.z; xs[lk+3][lm] = xv.w;
        wsm[lk+0][lm] = wv.x; wsm[lk+1][lm] = wv.y; wsm[lk+2][lm] = wv.z; wsm[lk+3][lm] = wv.w;
        __syncthreads();
#pragma unroll
        for (int k = 0; k < 8; k++) {
            float a[8], bb[8];
            *(float4*)&a[0]  = *(const float4*)&xs[k][ty * 4];
            *(float4*)&a[4]  = *(const float4*)&xs[k][64 + ty * 4];
            *(float4*)&bb[0] = *(const float4*)&wsm[k][tx * 4];
            *(float4*)&bb[4] = *(const float4*)&wsm[k][64 + tx * 4];
#pragma unroll
            for (int i = 0; i < 8; i++)
#pragma unroll
                for (int jn = 0; jn < 8; jn++)
                    acc[i][jn] += a[i] * bb[jn];
        }
        __syncthreads();
    }

    // bias per output column
    float bias[8];
#pragma unroll
    for (int jn = 0; jn < 8; jn++) {
        int col = (jn < 4) ? (tx * 4 + jn) : (64 + tx * 4 + (jn - 4));
        bias[jn] = bih[nb + col] + bhh[nb + col];
    }

#pragma unroll
    for (int i = 0; i < 8; i++) {
        int m_local = (i < 4) ? (ty * 4 + i) : (64 + ty * 4 + (i - 4));
        size_t row = (mb + m_local) * (size_t)G4 + nb;
        float4 v0, v1;
        v0.x = acc[i][0] + bias[0]; v0.y = acc[i][1] + bias[1];
        v0.z = acc[i][2] + bias[2]; v0.w = acc[i][3] + bias[3];
        v1.x = acc[i][4] + bias[4]; v1.y = acc[i][5] + bias[5];
        v1.z = acc[i][6] + bias[6]; v1.w = acc[i][7] + bias[7];
        *(float4*)&g_xproj[row + tx * 4]      = v0;
        *(float4*)&g_xproj[row + 64 + tx * 4] = v1;
    }
}

// ================= persistent recurrent kernel =================

__device__ __forceinline__ void grid_barrier() {
    __syncthreads();
    if (threadIdx.x == 0) {
        unsigned my = *(volatile unsigned*)&g_gen;
        __threadfence();
        unsigned arrived = atomicAdd(&g_count, 1u);
        if (arrived == NBLK - 1) {
            g_count = 0;
            __threadfence();
            atomicAdd(&g_gen, 1u);
        } else {
            while (*(volatile unsigned*)&g_gen == my) { __nanosleep(64); }
        }
        __threadfence();
    }
    __syncthreads();
}

__device__ __forceinline__ float sigmoidf_(float x) {
    return 1.0f / (1.0f + expf(-x));
}

// Block blk owns h-columns [blk*NH, blk*NH+8). Thread (j = tid&7, ty = tid>>3):
// h-index hb+j, batch rows 2*ty and 2*ty+1, all four gates. c lives in registers.
__global__ __launch_bounds__(256) void lstm_recurrent(
    const float* __restrict__ h0in,
    const float* __restrict__ c0in,
    const float* __restrict__ whh,   // [4096][1024]
    float* __restrict__ out,
    int out_size)
{
    __shared__ float hs[KT][66];     // hs[k][b]
    __shared__ float ws[KT][36];     // ws[k][j*4+g]

    const int tid = threadIdx.x;
    const int blk = blockIdx.x;
    const int hb  = blk * NH;
    const int j   = tid & 7;
    const int ty  = tid >> 3;        // 0..31
    const int b0  = 2 * ty;
    const int b1  = 2 * ty + 1;

    // weight-load assignment: cidx = j*4+g column in smem
    const int cidx = tid >> 3;             // 0..31
    const int jj   = cidx >> 2;
    const int gg   = cidx & 3;
    const int kqw  = (tid & 7) * 4;        // k offset in tile
    const size_t wbase = (size_t)(gg * HID + hb + jj) * HID + kqw;

    float creg0 = c0in[b0 * HID + hb + j];
    float creg1 = c0in[b1 * HID + hb + j];

    for (int t = 0; t < T_STEPS; t++) {
        const float* __restrict__ hread = (t == 0) ? h0in : g_h[t & 1];
        const float* xp = &g_xproj[(size_t)t * BATCH * G4];

        // init accumulators from x projection (issues LDGs early)
        float acc0[4], acc1[4];
#pragma unroll
        for (int g = 0; g < 4; g++) {
            acc0[g] = xp[(size_t)b0 * G4 + g * HID + hb + j];
            acc1[g] = xp[(size_t)b1 * G4 + g * HID + hb + j];
        }

        for (int k0 = 0; k0 < HID; k0 += KT) {
            // load h tile: 64 rows x 32 k  (2048 floats, 2 float4 per thread)
#pragma unroll
            for (int q = 0; q < 2; q++) {
                int s  = tid * 2 + q;
                int b  = s >> 3;
                int kq = (s & 7) * 4;
                float4 v = *(const float4*)&hread[b * HID + k0 + kq];
                hs[kq+0][b] = v.x; hs[kq+1][b] = v.y;
                hs[kq+2][b] = v.z; hs[kq+3][b] = v.w;
            }
            // load w tile: 32 cols x 32 k (1 float4 per thread)
            {
                float4 wv = *(const float4*)&whh[wbase + k0];
                ws[kqw+0][cidx] = wv.x; ws[kqw+1][cidx] = wv.y;
                ws[kqw+2][cidx] = wv.z; ws[kqw+3][cidx] = wv.w;
            }
            __syncthreads();
#pragma unroll
            for (int k = 0; k < KT; k++) {
                float2 hv = *(const float2*)&hs[k][2 * ty];
                float4 wv = *(const float4*)&ws[k][4 * j];
                acc0[0] += hv.x * wv.x; acc0[1] += hv.x * wv.y;
                acc0[2] += hv.x * wv.z; acc0[3] += hv.x * wv.w;
                acc1[0] += hv.y * wv.x; acc1[1] += hv.y * wv.y;
                acc1[2] += hv.y * wv.z; acc1[3] += hv.y * wv.w;
            }
            __syncthreads();
        }

        // elementwise LSTM cell (gate order: i, f, g, o)
        float i0 = sigmoidf_(acc0[0]);
        float f0 = sigmoidf_(acc0[1]);
        float g0 = tanhf(acc0[2]);
        float o0 = sigmoidf_(acc0[3]);
        creg0 = f0 * creg0 + i0 * g0;
        float hv0 = o0 * tanhf(creg0);

        float i1 = sigmoidf_(acc1[0]);
        float f1 = sigmoidf_(acc1[1]);
        float g1 = tanhf(acc1[2]);
        float o1 = sigmoidf_(acc1[3]);
        creg1 = f1 * creg1 + i1 * g1;
        float hv1 = o1 * tanhf(creg1);

        float* hw = g_h[(t + 1) & 1];
        hw[b0 * HID + hb + j] = hv0;
        hw[b1 * HID + hb + j] = hv1;

        out[((size_t)t * BATCH + b0) * HID + hb + j] = hv0;
        out[((size_t)t * BATCH + b1) * HID + hb + j] = hv1;

        if (t == T_STEPS - 1) {
            const long long need = (long long)T_STEPS * BATCH * HID + 2LL * BATCH * HID;
            if ((long long)out_size >= need) {
                size_t base = (size_t)T_STEPS * BATCH * HID;
                out[base + b0 * HID + hb + j] = hv0;
                out[base + b1 * HID + hb + j] = hv1;
                out[base + (size_t)BATCH * HID + b0 * HID + hb + j] = creg0;
                out[base + (size_t)BATCH * HID + b1 * HID + hb + j] = creg1;
            }
        } else {
            grid_barrier();
        }
    }
}

// ================= launch =================
extern "C" void kernel_launch(void* const* d_in, const int* in_sizes, int n_in,
                              void* d_out, int out_size) {
    const float* x    = (const float*)d_in[0];  // [T,B,I]
    const float* h0   = (const float*)d_in[1];  // [B,H]
    const float* c0   = (const float*)d_in[2];  // [B,H]
    const float* w_ih = (const float*)d_in[3];  // [4H,I]
    const float* w_hh = (const float*)d_in[4];  // [4H,H]
    const float* b_ih = (const float*)d_in[5];  // [4H]
    const float* b_hh = (const float*)d_in[6];  // [4H]
    float* out = (float*)d_out;

    dim3 g1(G4 / 128, (T_STEPS * BATCH) / 128);   // 32 x 512
    xproj_kernel<<<g1, 256>>>(x, w_ih, b_ih, b_hh);
    lstm_recurrent<<<NBLK, 256>>>(h0, c0, w_hh, out, out_size);
}

// round 4
// speedup vs baseline: 2.1870x; 2.1838x over previous
#include <cuda_runtime.h>
#include <cuda_bf16.h>
#include <math.h>
#include <stdint.h>

#define T_STEPS 1024
#define BATCH   64
#define INDIM   512
#define HID     1024
#define G4      4096

#define NBLK 128

// ---------------- device scratch (static) ----------------
__device__ float          g_xproj[(size_t)T_STEPS * BATCH * G4];   // [T][B][4H]
__device__ __nv_bfloat16  g_xhi[(size_t)T_STEPS * BATCH * INDIM];
__device__ __nv_bfloat16  g_xlo[(size_t)T_STEPS * BATCH * INDIM];
__device__ __nv_bfloat16  g_wihhi[(size_t)G4 * INDIM];
__device__ __nv_bfloat16  g_wihlo[(size_t)G4 * INDIM];
__device__ __nv_bfloat16  g_hhi[2][BATCH * HID];
__device__ __nv_bfloat16  g_hlo[2][BATCH * HID];
__device__ unsigned g_gen   = 0;
__device__ unsigned g_count = 0;

// ---------------- helpers ----------------
__device__ __forceinline__ uint32_t smem_u32(const void* p) {
    uint32_t a;
    asm("{ .reg .u64 t; cvta.to.shared.u64 t, %1; cvt.u32.u64 %0, t; }" : "=r"(a) : "l"(p));
    return a;
}

__device__ __forceinline__ void ldsm_x4(uint32_t& r0, uint32_t& r1, uint32_t& r2, uint32_t& r3,
                                        uint32_t addr) {
    asm volatile("ldmatrix.sync.aligned.m8n8.x4.shared.b16 {%0,%1,%2,%3}, [%4];"
                 : "=r"(r0), "=r"(r1), "=r"(r2), "=r"(r3) : "r"(addr));
}

__device__ __forceinline__ void mma_bf16(float& d0, float& d1, float& d2, float& d3,
                                         uint32_t a0, uint32_t a1, uint32_t a2, uint32_t a3,
                                         uint32_t b0, uint32_t b1) {
    asm volatile(
        "mma.sync.aligned.m16n8k16.row.col.f32.bf16.bf16.f32 "
        "{%0,%1,%2,%3}, {%4,%5,%6,%7}, {%8,%9}, {%0,%1,%2,%3};"
        : "+f"(d0), "+f"(d1), "+f"(d2), "+f"(d3)
        : "r"(a0), "r"(a1), "r"(a2), "r"(a3), "r"(b0), "r"(b1));
}

// fp32x4 -> packed bf16 hi (uint2) and lo residual (uint2)
__device__ __forceinline__ void split4(float4 v, uint2& hip, uint2& lop) {
    __nv_bfloat16 hx = __float2bfloat16_rn(v.x);
    __nv_bfloat16 hy = __float2bfloat16_rn(v.y);
    __nv_bfloat16 hz = __float2bfloat16_rn(v.z);
    __nv_bfloat16 hw = __float2bfloat16_rn(v.w);
    __nv_bfloat162 p0 = __halves2bfloat162(hx, hy);
    __nv_bfloat162 p1 = __halves2bfloat162(hz, hw);
    hip.x = *reinterpret_cast<unsigned*>(&p0);
    hip.y = *reinterpret_cast<unsigned*>(&p1);
    __nv_bfloat162 q0 = __floats2bfloat162_rn(v.x - __bfloat162float(hx),
                                              v.y - __bfloat162float(hy));
    __nv_bfloat162 q1 = __floats2bfloat162_rn(v.z - __bfloat162float(hz),
                                              v.w - __bfloat162float(hw));
    lop.x = *reinterpret_cast<unsigned*>(&q0);
    lop.y = *reinterpret_cast<unsigned*>(&q1);
}

__device__ __forceinline__ float sigmoidf_(float x) { return 1.0f / (1.0f + __expf(-x)); }

__device__ __forceinline__ void grid_barrier() {
    __syncthreads();
    if (threadIdx.x == 0) {
        unsigned my = *(volatile unsigned*)&g_gen;
        __threadfence();
        unsigned arrived = atomicAdd(&g_count, 1u);
        if (arrived == NBLK - 1) {
            g_count = 0;
            __threadfence();
            atomicAdd(&g_gen, 1u);
        } else {
            while (*(volatile unsigned*)&g_gen == my) { __nanosleep(32); }
        }
        __threadfence();
    }
    __syncthreads();
}

// ================= split pass: x, w_ih, h0 -> bf16 hi/lo =================
__global__ __launch_bounds__(256) void split_inputs(
    const float* __restrict__ x,
    const float* __restrict__ wih,
    const float* __restrict__ h0)
{
    const size_t NX = (size_t)T_STEPS * BATCH * INDIM / 4;   // float4 count
    const size_t NW = (size_t)G4 * INDIM / 4;
    const size_t NH0 = (size_t)BATCH * HID / 4;
    const size_t total = NX + NW + NH0;
    for (size_t i = (size_t)blockIdx.x * blockDim.x + threadIdx.x;
         i < total; i += (size_t)gridDim.x * blockDim.x) {
        if (i < NX) {
            float4 v = ((const float4*)x)[i];
            uint2 h, l; split4(v, h, l);
            ((uint2*)g_xhi)[i] = h;
            ((uint2*)g_xlo)[i] = l;
        } else if (i < NX + NW) {
            size_t k = i - NX;
            float4 v = ((const float4*)wih)[k];
            uint2 h, l; split4(v, h, l);
            ((uint2*)g_wihhi)[k] = h;
            ((uint2*)g_wihlo)[k] = l;
        } else {
            size_t k = i - NX - NW;
            float4 v = ((const float4*)h0)[k];
            uint2 h, l; split4(v, h, l);
            ((uint2*)g_hhi[0])[k] = h;
            ((uint2*)g_hlo[0])[k] = l;
        }
    }
}

// ================= x_proj GEMM (bf16-split HMMA) =================
// C[m][n] = x[m][:] . w_ih[n][:] + bih[n] + bhh[n]
// M=65536, N=4096, K=512. CTA tile 128x128, k-chunk 64, 8 warps (2m x 4n),
// warp tile 64x32.
#define XP_ROWB 144                 // 72 bf16 per row (64 + 8 pad)
#define XP_TILE (128 * XP_ROWB)     // 18432
#define XP_BUF  (4 * XP_TILE)       // Ahi,Alo,Bhi,Blo = 73728
#define XP_SMEM (2 * XP_BUF)        // 147456

__global__ __launch_bounds__(256) void xproj_mma(
    const float* __restrict__ bih,
    const float* __restrict__ bhh)
{
    extern __shared__ char smem[];
    const uint32_t sb = smem_u32(smem);
    const int tid  = threadIdx.x;
    const int lane = tid & 31;
    const int w    = tid >> 5;
    const int wm   = w & 1;          // m half (64 rows)
    const int wn   = w >> 1;         // n quarter (32 cols)
    const int nb   = blockIdx.x * 128;
    const size_t mb = (size_t)blockIdx.y * 128;

    float acc[4][4][4];
#pragma unroll
    for (int a = 0; a < 4; a++)
#pragma unroll
        for (int b = 0; b < 4; b++)
#pragma unroll
            for (int c = 0; c < 4; c++) acc[a][b][c] = 0.f;

    // per-thread staging map: 4 iterations, each copies Ahi/Alo/Bhi/Blo sector
    const int srow = (tid * 4) >> 3;        // base handled below per q

    // ldmatrix per-lane address components
    const int a_row = wm * 64 + (lane & 7) + ((lane >> 3) & 1) * 8;  // + mt*16
    const int a_k8  = (lane >> 4) * 8;                               // + s*16
    const int b_row = wn * 32 + (lane & 7) + (lane >> 4) * 8;        // + pair*16
    const int b_k8  = ((lane >> 3) & 1) * 8;

    for (int kb = 0; kb < 8; kb++) {
        const int buf = kb & 1;
        char* base = smem + buf * XP_BUF;
        // stage chunk kb
#pragma unroll
        for (int q = 0; q < 4; q++) {
            int s   = tid * 4 + q;      // 0..1023
            int row = s >> 3;
            int c   = s & 7;
            size_t gk = (size_t)kb * 64 + c * 8;
            *(uint4*)(base + 0 * XP_TILE + row * XP_ROWB + c * 16) =
                *(const uint4*)&g_xhi[(mb + row) * INDIM + gk];
            *(uint4*)(base + 1 * XP_TILE + row * XP_ROWB + c * 16) =
                *(const uint4*)&g_xlo[(mb + row) * INDIM + gk];
            *(uint4*)(base + 2 * XP_TILE + row * XP_ROWB + c * 16) =
                *(const uint4*)&g_wihhi[(size_t)(nb + row) * INDIM + gk];
            *(uint4*)(base + 3 * XP_TILE + row * XP_ROWB + c * 16) =
                *(const uint4*)&g_wihlo[(size_t)(nb + row) * INDIM + gk];
        }
        __syncthreads();

        const uint32_t aHi = sb + buf * XP_BUF;
        const uint32_t aLo = aHi + XP_TILE;
        const uint32_t bHi = aHi + 2 * XP_TILE;
        const uint32_t bLo = aHi + 3 * XP_TILE;

#pragma unroll
        for (int s = 0; s < 4; s++) {
            // B fragments: 4 n-tiles (2 ldsm.x4 each for hi and lo)
            uint32_t bh[8], bl[8];
#pragma unroll
            for (int p = 0; p < 2; p++) {
                uint32_t off = (b_row + p * 16) * XP_ROWB + (s * 16 + b_k8) * 2;
                ldsm_x4(bh[p*4+0], bh[p*4+1], bh[p*4+2], bh[p*4+3], bHi + off);
                ldsm_x4(bl[p*4+0], bl[p*4+1], bl[p*4+2], bl[p*4+3], bLo + off);
            }
#pragma unroll
            for (int mt = 0; mt < 4; mt++) {
                uint32_t off = (a_row + mt * 16) * XP_ROWB + (s * 16 + a_k8) * 2;
                uint32_t ah0, ah1, ah2, ah3, al0, al1, al2, al3;
                ldsm_x4(ah0, ah1, ah2, ah3, aHi + off);
                ldsm_x4(al0, al1, al2, al3, aLo + off);
#pragma unroll
                for (int nt = 0; nt < 4; nt++) {
                    float* d = acc[mt][nt];
                    mma_bf16(d[0], d[1], d[2], d[3], ah0, ah1, ah2, ah3, bh[nt*2], bh[nt*2+1]);
                    mma_bf16(d[0], d[1], d[2], d[3], ah0, ah1, ah2, ah3, bl[nt*2], bl[nt*2+1]);
                    mma_bf16(d[0], d[1], d[2], d[3], al0, al1, al2, al3, bh[nt*2], bh[nt*2+1]);
                }
            }
        }
        __syncthreads();
    }

    // epilogue: add bias, store fp32
    const int colq = (lane & 3) * 2;
#pragma unroll
    for (int nt = 0; nt < 4; nt++) {
        int col = nb + wn * 32 + nt * 8 + colq;
        float b0 = bih[col] + bhh[col];
        float b1 = bih[col + 1] + bhh[col + 1];
#pragma unroll
        for (int mt = 0; mt < 4; mt++) {
            size_t r0 = mb + wm * 64 + mt * 16 + (lane >> 2);
            float2 v0 = make_float2(acc[mt][nt][0] + b0, acc[mt][nt][1] + b1);
            float2 v1 = make_float2(acc[mt][nt][2] + b0, acc[mt][nt][3] + b1);
            *(float2*)&g_xproj[r0 * G4 + col]       = v0;
            *(float2*)&g_xproj[(r0 + 8) * G4 + col] = v1;
        }
    }
    (void)srow;
}

// ================= persistent recurrent kernel (bf16-split HMMA) =================
// CTA owns 32 N cols (n_local = g*8+j, global col g*1024+hb+j), M=64 batch, K=1024.
// Whh hi/lo resident in SMEM. h broadcast via g_hhi/g_hlo (pre-split, dbl-buffered).
#define R_WROW  2064                   // 1032 bf16 per row
#define R_W     (32 * R_WROW)          // 66048
#define SM_WHI  0
#define SM_WLO  R_W
#define R_AROW  144                    // 72 bf16
#define R_ATILE (64 * R_AROW)          // 9216
#define SM_A    (2 * R_W)              // 132096 ; 2buf x (hi,lo)
#define SM_GS   (SM_A + 4 * R_ATILE)   // 168960 ; gate smem 64x33 fp32
#define R_SMEM  (SM_GS + 64 * 33 * 4)  // 177408

__global__ __launch_bounds__(256, 1) void lstm_rec_mma(
    const float* __restrict__ c0in,
    const float* __restrict__ whh,
    float* __restrict__ out, int out_size)
{
    extern __shared__ char smem[];
    const uint32_t sb = smem_u32(smem);
    float* gs = (float*)(smem + SM_GS);
    const int tid  = threadIdx.x;
    const int lane = tid & 31;
    const int w    = tid >> 5;
    const int mt   = w & 3;            // batch tile (16 rows)
    const int nh   = w >> 2;           // n half (16 cols)
    const int hb   = blockIdx.x * 8;

    // one-time: split W_hh slice into SMEM (rows n_local=g*8+j)
    for (int it = 0; it < 32; it++) {
        int e4 = it * 256 + tid;           // 0..8191 float4
        int n  = e4 >> 8;                  // 0..31
        int kf = (e4 & 255) * 4;
        int g  = n >> 3, j = n & 7;
        float4 v = *(const float4*)&whh[(size_t)(g * HID + hb + j) * HID + kf];
        uint2 hp, lp; split4(v, hp, lp);
        *(uint2*)(smem + SM_WHI + n * R_WROW + kf * 2) = hp;
        *(uint2*)(smem + SM_WLO + n * R_WROW + kf * 2) = lp;
    }
    __syncthreads();

    // ldsm address components
    const int a_row = mt * 16 + (lane & 7) + ((lane >> 3) & 1) * 8;
    const int a_k8  = (lane >> 4) * 8;
    const int b_row = nh * 16 + (lane & 7) + (lane >> 4) * 8;
    const int b_k8  = ((lane >> 3) & 1) * 8;

    // cell state: thread handles pairs p0=tid, p1=tid+256 -> (b = p>>3, j = p&7)
    const int b0p = tid >> 3, j0p = tid & 7;
    const int b1p = (tid + 256) >> 3, j1p = tid & 7;
    float creg0 = c0in[b0p * HID + hb + j0p];
    float creg1 = c0in[b1p * HID + hb + j1p];

    for (int t = 0; t < T_STEPS; t++) {
        const int rbuf = t & 1;
        const __nv_bfloat16* hhi = g_hhi[rbuf];
        const __nv_bfloat16* hlo = g_hlo[rbuf];

        // prefetch x-projection gates for this thread's (b,j) pairs
        float xg0[4], xg1[4];
        {
            const float* xp = g_xproj + (size_t)t * BATCH * G4;
#pragma unroll
            for (int g = 0; g < 4; g++) {
                xg0[g] = xp[(size_t)b0p * G4 + g * HID + hb + j0p];
                xg1[g] = xp[(size_t)b1p * G4 + g * HID + hb + j1p];
            }
        }

        float acc[2][4];
#pragma unroll
        for (int p = 0; p < 2; p++)
#pragma unroll
            for (int c = 0; c < 4; c++) acc[p][c] = 0.f;

        // stage chunk 0
        {
#pragma unroll
            for (int q = 0; q < 2; q++) {
                int s = tid * 2 + q, b = s >> 3, c = s & 7;
                *(uint4*)(smem + SM_A + b * R_AROW + c * 16) =
                    *(const uint4*)&hhi[b * HID + c * 8];
                *(uint4*)(smem + SM_A + R_ATILE + b * R_AROW + c * 16) =
                    *(const uint4*)&hlo[b * HID + c * 8];
            }
        }
        __syncthreads();

        for (int kb = 0; kb < 16; kb++) {
            const int buf = kb & 1;
            if (kb < 15) {   // stage next chunk into other buffer
                const int nbuf = buf ^ 1;
                const int k0 = (kb + 1) * 64;
#pragma unroll
                for (int q = 0; q < 2; q++) {
                    int s = tid * 2 + q, b = s >> 3, c = s & 7;
                    *(uint4*)(smem + SM_A + nbuf * 2 * R_ATILE + b * R_AROW + c * 16) =
                        *(const uint4*)&hhi[b * HID + k0 + c * 8];
                    *(uint4*)(smem + SM_A + nbuf * 2 * R_ATILE + R_ATILE + b * R_AROW + c * 16) =
                        *(const uint4*)&hlo[b * HID + k0 + c * 8];
                }
            }
            const uint32_t aHi = sb + SM_A + buf * 2 * R_ATILE;
            const uint32_t aLo = aHi + R_ATILE;
#pragma unroll
            for (int s = 0; s < 4; s++) {
                uint32_t aoff = a_row * R_AROW + (s * 16 + a_k8) * 2;
                uint32_t ah0, ah1, ah2, ah3, al0, al1, al2, al3;
                ldsm_x4(ah0, ah1, ah2, ah3, aHi + aoff);
                ldsm_x4(al0, al1, al2, al3, aLo + aoff);
                uint32_t boff = b_row * R_WROW + (kb * 64 + s * 16 + b_k8) * 2;
                uint32_t bh0, bh1, bh2, bh3, bl0, bl1, bl2, bl3;
                ldsm_x4(bh0, bh1, bh2, bh3, sb + SM_WHI + boff);
                ldsm_x4(bl0, bl1, bl2, bl3, sb + SM_WLO + boff);
                mma_bf16(acc[0][0], acc[0][1], acc[0][2], acc[0][3],
                         ah0, ah1, ah2, ah3, bh0, bh1);
                mma_bf16(acc[0][0], acc[0][1], acc[0][2], acc[0][3],
                         ah0, ah1, ah2, ah3, bl0, bl1);
                mma_bf16(acc[0][0], acc[0][1], acc[0][2], acc[0][3],
                         al0, al1, al2, al3, bh0, bh1);
                mma_bf16(acc[1][0], acc[1][1], acc[1][2], acc[1][3],
                         ah0, ah1, ah2, ah3, bh2, bh3);
                mma_bf16(acc[1][0], acc[1][1], acc[1][2], acc[1][3],
                         ah0, ah1, ah2, ah3, bl2, bl3);
                mma_bf16(acc[1][0], acc[1][1], acc[1][2], acc[1][3],
                         al0, al1, al2, al3, bh2, bh3);
            }
            __syncthreads();
        }

        // scatter C fragments to gate smem: gs[b][n_local], pad 33
        {
            int r = mt * 16 + (lane >> 2);
            int cq = (lane & 3) * 2;
#pragma unroll
            for (int nt = 0; nt < 2; nt++) {
                int col = nh * 16 + nt * 8 + cq;
                gs[r * 33 + col]           = acc[nt][0];
                gs[r * 33 + col + 1]       = acc[nt][1];
                gs[(r + 8) * 33 + col]     = acc[nt][2];
                gs[(r + 8) * 33 + col + 1] = acc[nt][3];
            }
        }
        __syncthreads();

        // cell update for 2 (b,j) pairs
        const int wbuf = (t + 1) & 1;
        float hv0, hv1;
        {
            float ig = sigmoidf_(gs[b0p * 33 + 0 * 8 + j0p] + xg0[0]);
            float fg = sigmoidf_(gs[b0p * 33 + 1 * 8 + j0p] + xg0[1]);
            float gg = tanhf    (gs[b0p * 33 + 2 * 8 + j0p] + xg0[2]);
            float og = sigmoidf_(gs[b0p * 33 + 3 * 8 + j0p] + xg0[3]);
            creg0 = fg * creg0 + ig * gg;
            hv0 = og * tanhf(creg0);
            float ig1 = sigmoidf_(gs[b1p * 33 + 0 * 8 + j1p] + xg1[0]);
            float fg1 = sigmoidf_(gs[b1p * 33 + 1 * 8 + j1p] + xg1[1]);
            float gg1 = tanhf    (gs[b1p * 33 + 2 * 8 + j1p] + xg1[2]);
            float og1 = sigmoidf_(gs[b1p * 33 + 3 * 8 + j1p] + xg1[3]);
            creg1 = fg1 * creg1 + ig1 * gg1;
            hv1 = og1 * tanhf(creg1);

            __nv_bfloat16 h0h = __float2bfloat16_rn(hv0);
            __nv_bfloat16 h1h = __float2bfloat16_rn(hv1);
            g_hhi[wbuf][b0p * HID + hb + j0p] = h0h;
            g_hhi[wbuf][b1p * HID + hb + j1p] = h1h;
            g_hlo[wbuf][b0p * HID + hb + j0p] =
                __float2bfloat16_rn(hv0 - __bfloat162float(h0h));
            g_hlo[wbuf][b1p * HID + hb + j1p] =
                __float2bfloat16_rn(hv1 - __bfloat162float(h1h));

            out[((size_t)t * BATCH + b0p) * HID + hb + j0p] = hv0;
            out[((size_t)t * BATCH + b1p) * HID + hb + j1p] = hv1;
        }

        if (t == T_STEPS - 1) {
            const long long need = (long long)T_STEPS * BATCH * HID + 2LL * BATCH * HID;
            if ((long long)out_size >= need) {
                size_t base = (size_t)T_STEPS * BATCH * HID;
                out[base + (size_t)b0p * HID + hb + j0p] = hv0;
                out[base + (size_t)b1p * HID + hb + j1p] = hv1;
                out[base + (size_t)BATCH * HID + (size_t)b0p * HID + hb + j0p] = creg0;
                out[base + (size_t)BATCH * HID + (size_t)b1p * HID + hb + j1p] = creg1;
            }
        } else {
            grid_barrier();
        }
    }
}

// ================= launch =================
extern "C" void kernel_launch(void* const* d_in, const int* in_sizes, int n_in,
                              void* d_out, int out_size) {
    const float* x    = (const float*)d_in[0];
    const float* h0   = (const float*)d_in[1];
    const float* c0   = (const float*)d_in[2];
    const float* w_ih = (const float*)d_in[3];
    const float* w_hh = (const float*)d_in[4];
    const float* b_ih = (const float*)d_in[5];
    const float* b_hh = (const float*)d_in[6];
    float* out = (float*)d_out;

    cudaFuncSetAttribute(xproj_mma,
                         cudaFuncAttributeMaxDynamicSharedMemorySize, XP_SMEM);
    cudaFuncSetAttribute(lstm_rec_mma,
                         cudaFuncAttributeMaxDynamicSharedMemorySize, R_SMEM);

    split_inputs<<<2048, 256>>>(x, w_ih, h0);
    dim3 gx(G4 / 128, (T_STEPS * BATCH) / 128);   // 32 x 512
    xproj_mma<<<gx, 256, XP_SMEM>>>(b_ih, b_hh);
    lstm_rec_mma<<<NBLK, 256, R_SMEM>>>(c0, w_hh, out, out_size);
}

// round 5
// speedup vs baseline: 2.4470x; 1.1189x over previous
#include <cuda_runtime.h>
#include <cuda_bf16.h>
#include <math.h>
#include <stdint.h>

#define T_STEPS 1024
#define BATCH   64
#define INDIM   512
#define HID     1024
#define G4      4096

#define NBLK 128

// recurrent kernel geometry
#define CHUNKS  8
#define CKROWS  128                  // k rows per chunk
#define AROWB   144                  // 72 bf16 per k-row (64 b + 8 pad)
#define APLANE  (CKROWS * AROWB)     // 18432 bytes
#define ABUF    (2 * APLANE)         // hi+lo = 36864
#define WROWB   2064                 // 1032 bf16 per W row (1024 + 8 pad)
#define WPLANE  (32 * WROWB)         // 66048
#define SM_W    0
#define SM_AB   (2 * WPLANE)         // 132096
#define SM_MB   (SM_AB + 2 * ABUF)   // 205824
#define R_SMEM  (SM_MB + 64)         // 205888

// ---------------- device scratch (static) ----------------
__device__ float          g_xproj[(size_t)T_STEPS * BATCH * G4];   // [t][b][j*4+gate]
__device__ __nv_bfloat16  g_xhi[(size_t)T_STEPS * BATCH * INDIM];
__device__ __nv_bfloat16  g_xlo[(size_t)T_STEPS * BATCH * INDIM];
__device__ __nv_bfloat16  g_wihhi[(size_t)G4 * INDIM];
__device__ __nv_bfloat16  g_wihlo[(size_t)G4 * INDIM];
__device__ __nv_bfloat16  g_hT[2][2][HID][72];   // [buf][hi/lo][k][b(+pad)]
__device__ int            g_flags[NBLK];

// ---------------- helpers ----------------
__device__ __forceinline__ uint32_t smem_u32(const void* p) {
    uint32_t a;
    asm("{ .reg .u64 t; cvta.to.shared.u64 t, %1; cvt.u32.u64 %0, t; }" : "=r"(a) : "l"(p));
    return a;
}

#define LDSM_X4(r0,r1,r2,r3,addr) \
    asm volatile("ldmatrix.sync.aligned.m8n8.x4.shared.b16 {%0,%1,%2,%3}, [%4];" \
                 : "=r"(r0), "=r"(r1), "=r"(r2), "=r"(r3) : "r"(addr))

#define LDSM_X4T(r0,r1,r2,r3,addr) \
    asm volatile("ldmatrix.sync.aligned.m8n8.x4.trans.shared.b16 {%0,%1,%2,%3}, [%4];" \
                 : "=r"(r0), "=r"(r1), "=r"(r2), "=r"(r3) : "r"(addr))

__device__ __forceinline__ void mma_bf16(float& d0, float& d1, float& d2, float& d3,
                                         uint32_t a0, uint32_t a1, uint32_t a2, uint32_t a3,
                                         uint32_t b0, uint32_t b1) {
    asm volatile(
        "mma.sync.aligned.m16n8k16.row.col.f32.bf16.bf16.f32 "
        "{%0,%1,%2,%3}, {%4,%5,%6,%7}, {%8,%9}, {%0,%1,%2,%3};"
        : "+f"(d0), "+f"(d1), "+f"(d2), "+f"(d3)
        : "r"(a0), "r"(a1), "r"(a2), "r"(a3), "r"(b0), "r"(b1));
}

#define MBARRIER_INIT(mbar, count) \
    asm volatile("mbarrier.init.shared.b64 [%0], %1;" :: "r"((uint32_t)(mbar)), "r"((uint32_t)(count)) : "memory")

#define MBARRIER_EXPECT_TX(mbar, tx) \
    asm volatile("mbarrier.arrive.expect_tx.shared.b64 _, [%0], %1;" \
                 :: "r"((uint32_t)(mbar)), "r"((uint32_t)(tx)) : "memory")

#define MBARRIER_WAIT_PARITY(mbar_smem_addr, phase_parity) do { \
    uint32_t _mbar = (uint32_t)(mbar_smem_addr); \
    uint32_t _parity = (uint32_t)(phase_parity); \
    uint32_t _done; \
    asm volatile( \
        "{\n\t.reg .pred p;\n\t" \
        "mbarrier.try_wait.parity.acquire.cta.shared::cta.b64 p, [%1], %2;\n\t" \
        "selp.b32 %0, 1, 0, p;\n\t}" \
        : "=r"(_done) : "r"(_mbar), "r"(_parity) : "memory"); \
    if (!_done) { \
        asm volatile( \
            "{\n\t.reg .pred P1;\n\t" \
            "WAIT_LOOP_%=:\n\t" \
            "mbarrier.try_wait.parity.acquire.cta.shared::cta.b64 P1, [%0], %1, 0x989680;\n\t" \
            "@P1 bra.uni WAIT_DONE_%=;\n\t" \
            "bra.uni WAIT_LOOP_%=;\n\t" \
            "WAIT_DONE_%=:\n\t}" \
            :: "r"(_mbar), "r"(_parity) : "memory"); \
    } \
} while(0)

__device__ __forceinline__ void bulk_g2s(uint32_t dst, const void* src,
                                         uint32_t bytes, uint32_t mbar) {
    uint64_t gsrc;
    asm("cvta.to.global.u64 %0, %1;" : "=l"(gsrc) : "l"(src));
    asm volatile(
        "cp.async.bulk.shared::cluster.global.mbarrier::complete_tx::bytes [%0], [%1], %2, [%3];"
        :: "r"(dst), "l"(gsrc), "r"(bytes), "r"(mbar) : "memory");
}

// fp32x4 -> packed bf16 hi (uint2) and lo residual (uint2)
__device__ __forceinline__ void split4(float4 v, uint2& hip, uint2& lop) {
    __nv_bfloat16 hx = __float2bfloat16_rn(v.x);
    __nv_bfloat16 hy = __float2bfloat16_rn(v.y);
    __nv_bfloat16 hz = __float2bfloat16_rn(v.z);
    __nv_bfloat16 hw = __float2bfloat16_rn(v.w);
    __nv_bfloat162 p0 = __halves2bfloat162(hx, hy);
    __nv_bfloat162 p1 = __halves2bfloat162(hz, hw);
    hip.x = *reinterpret_cast<unsigned*>(&p0);
    hip.y = *reinterpret_cast<unsigned*>(&p1);
    __nv_bfloat162 q0 = __floats2bfloat162_rn(v.x - __bfloat162float(hx),
                                              v.y - __bfloat162float(hy));
    __nv_bfloat162 q1 = __floats2bfloat162_rn(v.z - __bfloat162float(hz),
                                              v.w - __bfloat162float(hw));
    lop.x = *reinterpret_cast<unsigned*>(&q0);
    lop.y = *reinterpret_cast<unsigned*>(&q1);
}

__device__ __forceinline__ float sigmoidf_(float x) { return 1.0f / (1.0f + __expf(-x)); }

// ================= split pass: x, w_ih, h0 -> bf16 hi/lo; reset flags =================
__global__ __launch_bounds__(256) void split_inputs(
    const float* __restrict__ x,
    const float* __restrict__ wih,
    const float* __restrict__ h0)
{
    if (blockIdx.x == 0 && threadIdx.x < NBLK) g_flags[threadIdx.x] = 0;

    const size_t NX  = (size_t)T_STEPS * BATCH * INDIM / 4;
    const size_t NW  = (size_t)G4 * INDIM / 4;
    const size_t NH0 = (size_t)BATCH * HID / 4;
    const size_t total = NX + NW + NH0;
    for (size_t i = (size_t)blockIdx.x * blockDim.x + threadIdx.x;
         i < total; i += (size_t)gridDim.x * blockDim.x) {
        if (i < NX) {
            float4 v = ((const float4*)x)[i];
            uint2 h, l; split4(v, h, l);
            ((uint2*)g_xhi)[i] = h;
            ((uint2*)g_xlo)[i] = l;
        } else if (i < NX + NW) {
            size_t k = i - NX;
            float4 v = ((const float4*)wih)[k];
            uint2 h, l; split4(v, h, l);
            ((uint2*)g_wihhi)[k] = h;
            ((uint2*)g_wihlo)[k] = l;
        } else {
            // h0 -> transposed split into g_hT[0]
            size_t e4 = i - NX - NW;          // 0..16383
            size_t e  = e4 * 4;
            int b = (int)(e >> 10);
            int k = (int)(e & 1023);
            float4 v = ((const float4*)h0)[e4];
            __nv_bfloat16 hi[4], lo[4];
            float vv[4] = {v.x, v.y, v.z, v.w};
#pragma unroll
            for (int q = 0; q < 4; q++) {
                hi[q] = __float2bfloat16_rn(vv[q]);
                lo[q] = __float2bfloat16_rn(vv[q] - __bfloat162float(hi[q]));
            }
#pragma unroll
            for (int q = 0; q < 4; q++) {
                g_hT[0][0][k + q][b] = hi[q];
                g_hT[0][1][k + q][b] = lo[q];
            }
        }
    }
}

// ================= x_proj GEMM (bf16-split HMMA, gate-interleaved output) =================
// Output layout: g_xproj[m][(jb+jl)*4 + gate]. Tile col nloc = jl*4+gate,
// W row for tile row r: (r&3)*1024 + jb + (r>>2).
#define XP_ROWB 144
#define XP_TILE (128 * XP_ROWB)
#define XP_BUF  (4 * XP_TILE)
#define XP_SMEM (2 * XP_BUF)

__global__ __launch_bounds__(256) void xproj_mma(
    const float* __restrict__ bih,
    const float* __restrict__ bhh)
{
    extern __shared__ char smem[];
    const uint32_t sb = smem_u32(smem);
    const int tid  = threadIdx.x;
    const int lane = tid & 31;
    const int w    = tid >> 5;
    const int wm   = w & 1;
    const int wn   = w >> 1;
    const int jb   = blockIdx.x * 32;          // j block (32 j values -> 128 cols)
    const size_t mb = (size_t)blockIdx.y * 128;

    float acc[4][4][4];
#pragma unroll
    for (int a = 0; a < 4; a++)
#pragma unroll
        for (int b = 0; b < 4; b++)
#pragma unroll
            for (int c = 0; c < 4; c++) acc[a][b][c] = 0.f;

    const int a_row = wm * 64 + (lane & 7) + ((lane >> 3) & 1) * 8;
    const int a_k8  = (lane >> 4) * 8;
    const int b_row = wn * 32 + (lane & 7) + (lane >> 4) * 8;
    const int b_k8  = ((lane >> 3) & 1) * 8;

    for (int kb = 0; kb < 8; kb++) {
        const int buf = kb & 1;
        char* base = smem + buf * XP_BUF;
#pragma unroll
        for (int q = 0; q < 4; q++) {
            int s   = tid * 4 + q;
            int row = s >> 3;
            int c   = s & 7;
            size_t gk = (size_t)kb * 64 + c * 8;
            int wrow = (row & 3) * HID + jb + (row >> 2);   // gate-interleaved W row
            *(uint4*)(base + 0 * XP_TILE + row * XP_ROWB + c * 16) =
                *(const uint4*)&g_xhi[(mb + row) * INDIM + gk];
            *(uint4*)(base + 1 * XP_TILE + row * XP_ROWB + c * 16) =
                *(const uint4*)&g_xlo[(mb + row) * INDIM + gk];
            *(uint4*)(base + 2 * XP_TILE + row * XP_ROWB + c * 16) =
                *(const uint4*)&g_wihhi[(size_t)wrow * INDIM + gk];
            *(uint4*)(base + 3 * XP_TILE + row * XP_ROWB + c * 16) =
                *(const uint4*)&g_wihlo[(size_t)wrow * INDIM + gk];
        }
        __syncthreads();

        const uint32_t aHi = sb + buf * XP_BUF;
        const uint32_t aLo = aHi + XP_TILE;
        const uint32_t bHi = aHi + 2 * XP_TILE;
        const uint32_t bLo = aHi + 3 * XP_TILE;

#pragma unroll
        for (int s = 0; s < 4; s++) {
            uint32_t bh[8], bl[8];
#pragma unroll
            for (int p = 0; p < 2; p++) {
                uint32_t off = (b_row + p * 16) * XP_ROWB + (s * 16 + b_k8) * 2;
                LDSM_X4(bh[p*4+0], bh[p*4+1], bh[p*4+2], bh[p*4+3], bHi + off);
                LDSM_X4(bl[p*4+0], bl[p*4+1], bl[p*4+2], bl[p*4+3], bLo + off);
            }
#pragma unroll
            for (int mt = 0; mt < 4; mt++) {
                uint32_t off = (a_row + mt * 16) * XP_ROWB + (s * 16 + a_k8) * 2;
                uint32_t ah0, ah1, ah2, ah3, al0, al1, al2, al3;
                LDSM_X4(ah0, ah1, ah2, ah3, aHi + off);
                LDSM_X4(al0, al1, al2, al3, aLo + off);
#pragma unroll
                for (int nt = 0; nt < 4; nt++) {
                    float* d = acc[mt][nt];
                    mma_bf16(d[0], d[1], d[2], d[3], ah0, ah1, ah2, ah3, bh[nt*2], bh[nt*2+1]);
                    mma_bf16(d[0], d[1], d[2], d[3], ah0, ah1, ah2, ah3, bl[nt*2], bl[nt*2+1]);
                    mma_bf16(d[0], d[1], d[2], d[3], al0, al1, al2, al3, bh[nt*2], bh[nt*2+1]);
                }
            }
        }
        __syncthreads();
    }

    // epilogue: bias (gate-mapped) + store (contiguous in new layout)
    const int colq = (lane & 3) * 2;
#pragma unroll
    for (int nt = 0; nt < 4; nt++) {
        int nloc = wn * 32 + nt * 8 + colq;         // tile-local col
        int g0 = nloc & 3,        j0 = jb + (nloc >> 2);
        int g1 = (nloc + 1) & 3,  j1 = jb + ((nloc + 1) >> 2);
        float bb0 = bih[g0 * HID + j0] + bhh[g0 * HID + j0];
        float bb1 = bih[g1 * HID + j1] + bhh[g1 * HID + j1];
#pragma unroll
        for (int mt = 0; mt < 4; mt++) {
            size_t r0 = mb + wm * 64 + mt * 16 + (lane >> 2);
            float2 v0 = make_float2(acc[mt][nt][0] + bb0, acc[mt][nt][1] + bb1);
            float2 v1 = make_float2(acc[mt][nt][2] + bb0, acc[mt][nt][3] + bb1);
            *(float2*)&g_xproj[r0 * G4 + jb * 4 + nloc]       = v0;
            *(float2*)&g_xproj[(r0 + 8) * G4 + jb * 4 + nloc] = v1;
        }
    }
}

// ================= persistent recurrent kernel (TMA-fed HMMA) =================
// CTA owns cols hb..hb+7 (j), x 4 gates = 32 N. N-order gate-interleaved so each
// thread's fragments hold all 4 gates of one (b,j): in-register cell update.
__global__ __launch_bounds__(256, 1) void lstm_rec_tma(
    const float* __restrict__ c0in,
    const float* __restrict__ whh,
    float* __restrict__ out, int out_size)
{
    extern __shared__ char smem[];
    const uint32_t sb = smem_u32(smem);
    const int tid  = threadIdx.x;
    const int lane = tid & 31;
    const int w    = tid >> 5;
    const int mt   = w & 3;            // 16 batch rows
    const int nh   = w >> 2;           // 16 N cols
    const int blk  = blockIdx.x;
    const int hb   = blk * 8;

    if (tid == 0) {
        MBARRIER_INIT(sb + SM_MB, 1);
        MBARRIER_INIT(sb + SM_MB + 8, 1);
    }
    asm volatile("fence.proxy.async.shared::cta;" ::: "memory");
    __syncthreads();

    // one-time: W slice -> smem (gate-interleaved rows), hi+lo
    for (int it = 0; it < 32; it++) {
        int e4 = it * 256 + tid;       // 8192 float4
        int n  = e4 >> 8;              // smem row 0..31
        int kf = (e4 & 255) * 4;
        int nh_ = n >> 4, r = n & 15;
        int nt = r >> 3, q = (r & 7) >> 1, low = r & 1;
        int gate = nt * 2 + low, j = 4 * nh_ + q;
        float4 v = *(const float4*)&whh[(size_t)(gate * HID + hb + j) * HID + kf];
        uint2 hp, lp; split4(v, hp, lp);
        *(uint2*)(smem + SM_W + n * WROWB + kf * 2) = hp;
        *(uint2*)(smem + SM_W + WPLANE + n * WROWB + kf * 2) = lp;
    }
    __syncthreads();

    // ldsm address components
    const uint32_t aK  = (lane & 7) + ((lane >> 4) << 3);           // k within k16
    const uint32_t aMb = (uint32_t)(mt * 16 + ((lane >> 3) & 1) * 8) * 2;
    const uint32_t bRowOff = (uint32_t)(nh * 16 + (lane & 7) + ((lane >> 4) << 3)) * WROWB;
    const uint32_t bK8 = ((lane >> 3) & 1) * 8;

    const int b0  = mt * 16 + (lane >> 2);
    const int b1  = b0 + 8;
    const int j   = 4 * nh + (lane & 3);
    const int col = hb + j;

    float c0r = c0in[b0 * HID + col];
    float c1r = c0in[b1 * HID + col];
    int ph0 = 0, ph1 = 0;

    for (int t = 0; t < T_STEPS; t++) {
        const __nv_bfloat16* hsrc = &g_hT[t & 1][0][0][0];   // hi plane; lo at +HID*72

        if (tid == 0) {
            MBARRIER_EXPECT_TX(sb + SM_MB, 2 * APLANE);
            bulk_g2s(sb + SM_AB,          hsrc,                    APLANE, sb + SM_MB);
            bulk_g2s(sb + SM_AB + APLANE, hsrc + (size_t)HID * 72, APLANE, sb + SM_MB);
            MBARRIER_EXPECT_TX(sb + SM_MB + 8, 2 * APLANE);
            bulk_g2s(sb + SM_AB + ABUF,          hsrc + 128 * 72,                    APLANE, sb + SM_MB + 8);
            bulk_g2s(sb + SM_AB + ABUF + APLANE, hsrc + (size_t)HID * 72 + 128 * 72, APLANE, sb + SM_MB + 8);
        }

        // prefetch gate biases from x projection ([b][(hb+j)*4 + gate])
        const float* xp = g_xproj + (size_t)t * BATCH * G4 + (size_t)col * 4;
        float4 xg0 = *(const float4*)(xp + (size_t)b0 * G4);
        float4 xg1 = *(const float4*)(xp + (size_t)b1 * G4);

        float am[2][4], ac[2][4];
#pragma unroll
        for (int p = 0; p < 2; p++)
#pragma unroll
            for (int c = 0; c < 4; c++) { am[p][c] = 0.f; ac[p][c] = 0.f; }

        for (int c = 0; c < CHUNKS; c++) {
            const int buf = c & 1;
            if (buf == 0) { MBARRIER_WAIT_PARITY(sb + SM_MB, ph0);     ph0 ^= 1; }
            else          { MBARRIER_WAIT_PARITY(sb + SM_MB + 8, ph1); ph1 ^= 1; }
            const uint32_t aHi = sb + SM_AB + buf * ABUF;
#pragma unroll
            for (int s = 0; s < 8; s++) {
                uint32_t ao = aHi + (s * 16 + aK) * AROWB + aMb;
                uint32_t ah0, ah1, ah2, ah3, al0, al1, al2, al3;
                LDSM_X4T(ah0, ah1, ah2, ah3, ao);
                LDSM_X4T(al0, al1, al2, al3, ao + APLANE);
                uint32_t bo = bRowOff + (uint32_t)((c * 128 + s * 16 + bK8) << 1);
                uint32_t bh0, bh1, bh2, bh3, bl0, bl1, bl2, bl3;
                LDSM_X4(bh0, bh1, bh2, bh3, sb + SM_W + bo);
                LDSM_X4(bl0, bl1, bl2, bl3, sb + SM_W + WPLANE + bo);
                // main product
                mma_bf16(am[0][0], am[0][1], am[0][2], am[0][3], ah0, ah1, ah2, ah3, bh0, bh1);
                mma_bf16(am[1][0], am[1][1], am[1][2], am[1][3], ah0, ah1, ah2, ah3, bh2, bh3);
                // corrections
                mma_bf16(ac[0][0], ac[0][1], ac[0][2], ac[0][3], ah0, ah1, ah2, ah3, bl0, bl1);
                mma_bf16(ac[0][0], ac[0][1], ac[0][2], ac[0][3], al0, al1, al2, al3, bh0, bh1);
                mma_bf16(ac[1][0], ac[1][1], ac[1][2], ac[1][3], ah0, ah1, ah2, ah3, bl2, bl3);
                mma_bf16(ac[1][0], ac[1][1], ac[1][2], ac[1][3], al0, al1, al2, al3, bh2, bh3);
            }
            __syncthreads();
            if (tid == 0 && c + 2 < CHUNKS) {
                uint32_t mb = sb + SM_MB + buf * 8;
                MBARRIER_EXPECT_TX(mb, 2 * APLANE);
                bulk_g2s(aHi,          hsrc + (size_t)(c + 2) * 128 * 72,                    APLANE, mb);
                bulk_g2s(aHi + APLANE, hsrc + (size_t)HID * 72 + (size_t)(c + 2) * 128 * 72, APLANE, mb);
            }
        }

        // in-register cell update (gates i,f at acc[0][*], g,o at acc[1][*])
        float ig0 = sigmoidf_(am[0][0] + ac[0][0] + xg0.x);
        float fg0 = sigmoidf_(am[0][1] + ac[0][1] + xg0.y);
        float gg0 = tanhf    (am[1][0] + ac[1][0] + xg0.z);
        float og0 = sigmoidf_(am[1][1] + ac[1][1] + xg0.w);
        c0r = fg0 * c0r + ig0 * gg0;
        float hv0 = og0 * tanhf(c0r);

        float ig1 = sigmoidf_(am[0][2] + ac[0][2] + xg1.x);
        float fg1 = sigmoidf_(am[0][3] + ac[0][3] + xg1.y);
        float gg1 = tanhf    (am[1][2] + ac[1][2] + xg1.z);
        float og1 = sigmoidf_(am[1][3] + ac[1][3] + xg1.w);
        c1r = fg1 * c1r + ig1 * gg1;
        float hv1 = og1 * tanhf(c1r);

        // write next h (transposed, split)
        const int wbuf = (t + 1) & 1;
        __nv_bfloat16 h0h = __float2bfloat16_rn(hv0);
        __nv_bfloat16 h1h = __float2bfloat16_rn(hv1);
        g_hT[wbuf][0][col][b0] = h0h;
        g_hT[wbuf][0][col][b1] = h1h;
        g_hT[wbuf][1][col][b0] = __float2bfloat16_rn(hv0 - __bfloat162float(h0h));
        g_hT[wbuf][1][col][b1] = __float2bfloat16_rn(hv1 - __bfloat162float(h1h));

        out[((size_t)t * BATCH + b0) * HID + col] = hv0;
        out[((size_t)t * BATCH + b1) * HID + col] = hv1;

        if (t == T_STEPS - 1) {
            const long long need = (long long)T_STEPS * BATCH * HID + 2LL * BATCH * HID;
            if ((long long)out_size >= need) {
                size_t base = (size_t)T_STEPS * BATCH * HID;
                out[base + (size_t)b0 * HID + col] = hv0;
                out[base + (size_t)b1 * HID + col] = hv1;
                out[base + (size_t)BATCH * HID + (size_t)b0 * HID + col] = c0r;
                out[base + (size_t)BATCH * HID + (size_t)b1 * HID + col] = c1r;
            }
        } else {
            // distributed-flag grid barrier
            __syncthreads();
            __threadfence();
            if (tid == 0) ((volatile int*)g_flags)[blk] = t + 1;
            if (tid < NBLK) {
                while (((volatile int*)g_flags)[tid] < t + 1) { __nanosleep(32); }
            }
            __threadfence();
            __syncthreads();
        }
    }
}

// ================= launch =================
extern "C" void kernel_launch(void* const* d_in, const int* in_sizes, int n_in,
                              void* d_out, int out_size) {
    const float* x    = (const float*)d_in[0];
    const float* h0   = (const float*)d_in[1];
    const float* c0   = (const float*)d_in[2];
    const float* w_ih = (const float*)d_in[3];
    const float* w_hh = (const float*)d_in[4];
    const float* b_ih = (const float*)d_in[5];
    const float* b_hh = (const float*)d_in[6];
    float* out = (float*)d_out;

    cudaFuncSetAttribute(xproj_mma,
                         cudaFuncAttributeMaxDynamicSharedMemorySize, XP_SMEM);
    cudaFuncSetAttribute(lstm_rec_tma,
                         cudaFuncAttributeMaxDynamicSharedMemorySize, R_SMEM);

    split_inputs<<<2048, 256>>>(x, w_ih, h0);
    dim3 gx(G4 / 128, (T_STEPS * BATCH) / 128);   // 32 x 512
    xproj_mma<<<gx, 256, XP_SMEM>>>(b_ih, b_hh);
    lstm_rec_tma<<<NBLK, 256, R_SMEM>>>(c0, w_hh, out, out_size);
}